// round 12
// baseline (speedup 1.0000x reference)
#include <cuda_runtime.h>
#include <cuda_fp16.h>
#include <math.h>

#define Bn 4
#define Hn 1080
#define Wn 1920
#define HWn (Hn * Wn)   // 2073600
#define NSPAN 60        // 1920 / 32 (bit-words per row)
#define NWRD  (Hn * NSPAN)
#define SPN   15        // 1920 / 128 (k2b warp spans)
#define KCH   4         // k2b rows per warp
#define NCHK  (Hn / KCH)  // 270

// ---------------- scratch (no runtime allocation allowed) ----------------
__device__ __align__(16) __half2 g_dc [Bn * HWn];   // (sqrt-diff, color-diff) fp16
__device__ __align__(16) float   g_gt [Bn * HWn];   // tgt gray fp32
__device__ __align__(16) __half2 g_hrt[Bn * HWn];   // (hsum7_ref, hsum7_tgt) fp16
__device__ __align__(16) unsigned g_edgew[Bn * NWRD];  // edge bits, 1/px
__device__ __align__(16) unsigned g_blkw [Bn * NWRD];  // blocking bits, 1/px
__device__ int   g_maxd_i;
__device__ int   g_maxcd_i;
__device__ float g_sum[Bn];
__device__ float g_invd, g_invcd;

static __forceinline__ __device__ unsigned h2u(__half2 h) {
    return *reinterpret_cast<unsigned*>(&h);
}

// ---------------- K0: zero reduction scalars ------------------------------
__global__ void k0_init() {
    int t = threadIdx.x;
    if (t == 0) g_maxd_i = 0;
    if (t == 1) g_maxcd_i = 0;
    if (t >= 2 && t < 2 + Bn) g_sum[t - 2] = 0.f;
}

// ---------------- K1: one row per block; pointwise + horizontal 7-sums ---
__global__ __launch_bounds__(480) void k1_point(const float* __restrict__ ref,
                                                const float* __restrict__ tgt) {
    const int y = blockIdx.x;
    const int b = blockIdx.y;
    const int t = threadIdx.x;           // 0..479

    __shared__ __align__(16) float srow_r[1928];   // 4 zero pad each side
    __shared__ __align__(16) float srow_t[1928];
    __shared__ float smx[15], smc[15], sms[15];

    if (t < 4) {
        srow_r[t] = 0.f; srow_t[t] = 0.f;
        srow_r[1924 + t] = 0.f; srow_t[1924 + t] = 0.f;
    }

    const size_t rowpx = (size_t)y * Wn + 4 * t;
    const int v = (int)(rowpx >> 2);

    const float4 r0 = ((const float4*)(ref + (size_t)(b * 3 + 0) * HWn))[v];
    const float4 r1 = ((const float4*)(ref + (size_t)(b * 3 + 1) * HWn))[v];
    const float4 r2 = ((const float4*)(ref + (size_t)(b * 3 + 2) * HWn))[v];
    const float4 t0 = ((const float4*)(tgt + (size_t)(b * 3 + 0) * HWn))[v];
    const float4 t1 = ((const float4*)(tgt + (size_t)(b * 3 + 1) * HWn))[v];
    const float4 t2 = ((const float4*)(tgt + (size_t)(b * 3 + 2) * HWn))[v];

    float4 D, C, GR, GT;
    float lmaxd = 0.f, lmaxcd = 0.f, lsum = 0.f;

#define LANE(c)                                                               \
    {                                                                         \
        float d0 = r0.c - t0.c, d1 = r1.c - t1.c, d2 = r2.c - t2.c;           \
        float df = sqrtf(d0 * d0 + d1 * d1 + d2 * d2);                        \
        float cd = (fabsf(d0) + fabsf(d1) + fabsf(d2)) * (1.f / 3.f);         \
        D.c = df; C.c = cd;                                                   \
        GR.c = 0.299f * r0.c + 0.587f * r1.c + 0.114f * r2.c;                 \
        GT.c = 0.299f * t0.c + 0.587f * t1.c + 0.114f * t2.c;                 \
        lmaxd = fmaxf(lmaxd, df); lmaxcd = fmaxf(lmaxcd, cd);                 \
        lsum += df;                                                           \
    }
    LANE(x) LANE(y) LANE(z) LANE(w)
#undef LANE

    uint4 dc;
    dc.x = h2u(__floats2half2_rn(D.x, C.x));
    dc.y = h2u(__floats2half2_rn(D.y, C.y));
    dc.z = h2u(__floats2half2_rn(D.z, C.z));
    dc.w = h2u(__floats2half2_rn(D.w, C.w));
    ((uint4*)(g_dc + (size_t)b * HWn))[v] = dc;
    ((float4*)(g_gt + (size_t)b * HWn))[v] = GT;

    *(float4*)&srow_r[4 + 4 * t] = GR;
    *(float4*)&srow_t[4 + 4 * t] = GT;

    #pragma unroll
    for (int o = 16; o > 0; o >>= 1) {
        lmaxd  = fmaxf(lmaxd,  __shfl_xor_sync(0xffffffffu, lmaxd,  o));
        lmaxcd = fmaxf(lmaxcd, __shfl_xor_sync(0xffffffffu, lmaxcd, o));
        lsum  +=               __shfl_xor_sync(0xffffffffu, lsum,   o);
    }
    const int lane = t & 31, wid = t >> 5;
    if (lane == 0) { smx[wid] = lmaxd; smc[wid] = lmaxcd; sms[wid] = lsum; }
    __syncthreads();
    if (t == 0) {
        float mx = smx[0], mc = smc[0], s = sms[0];
        #pragma unroll
        for (int i = 1; i < 15; i++) {
            mx = fmaxf(mx, smx[i]); mc = fmaxf(mc, smc[i]); s += sms[i];
        }
        atomicMax(&g_maxd_i,  __float_as_int(mx));
        atomicMax(&g_maxcd_i, __float_as_int(mc));
        atomicAdd(&g_sum[b], s);
    }

    const float* ar = srow_r + 4 * t;
    const float* at = srow_t + 4 * t;
    float4 A0 = *(const float4*)(ar), A1 = *(const float4*)(ar + 4), A2 = *(const float4*)(ar + 8);
    float4 B0 = *(const float4*)(at), B1 = *(const float4*)(at + 4), B2 = *(const float4*)(at + 8);
    float a[12] = {A0.x,A0.y,A0.z,A0.w, A1.x,A1.y,A1.z,A1.w, A2.x,A2.y,A2.z,A2.w};
    float c[12] = {B0.x,B0.y,B0.z,B0.w, B1.x,B1.y,B1.z,B1.w, B2.x,B2.y,B2.z,B2.w};

    float hr0 = a[1]+a[2]+a[3]+a[4]+a[5]+a[6]+a[7];
    float ht0 = c[1]+c[2]+c[3]+c[4]+c[5]+c[6]+c[7];
    float hr1 = hr0 + a[8] - a[1], ht1 = ht0 + c[8] - c[1];
    float hr2 = hr1 + a[9] - a[2], ht2 = ht1 + c[9] - c[2];
    float hr3 = hr2 + a[10] - a[3], ht3 = ht2 + c[10] - c[3];

    uint4 hq;
    hq.x = h2u(__floats2half2_rn(hr0, ht0));
    hq.y = h2u(__floats2half2_rn(hr1, ht1));
    hq.z = h2u(__floats2half2_rn(hr2, ht2));
    hq.w = h2u(__floats2half2_rn(hr3, ht3));
    ((uint4*)(g_hrt + (size_t)b * HWn))[v] = hq;
}

// ---------------- K2: score + inverse normalizers ------------------------
__global__ void k2_score(float* __restrict__ out) {
    const int t = threadIdx.x;
    const float invd  = 1.f / (__int_as_float(g_maxd_i)  + 1e-12f);
    const float invcd = 1.f / (__int_as_float(g_maxcd_i) + 1e-12f);
    if (t == 0) { g_invd = invd; g_invcd = invcd; }
    if (t < Bn) {
        float m = g_sum[t] * (1.f / (float)HWn) * invd;
        out[t] = fminf(fmaxf(1.f - m, 0.f), 1.f);
    }
}

// ---------------- K2b: vectorized Sobel -> edge/blocking bit-words ---------
// Warp = 128-col span (float4/thread) x KCH=4 rows. All 6 rows loaded UPFRONT
// (MLP=6) before shuffles/compute. 15 x 270 x 4 = 16200 warps = 2025 blocks.
__global__ __launch_bounds__(256, 6) void k2b_edge() {
    const int lane = threadIdx.x & 31;
    const int task = blockIdx.x * 8 + (threadIdx.x >> 5);
    if (task >= SPN * NCHK * Bn) return;
    const int s    = task % SPN;
    const int rem  = task / SPN;
    const int chnk = rem % NCHK;
    const int b    = rem / NCHK;
    const int yB   = chnk * KCH;
    const int x0v  = s * 128 + lane * 4;

    const float* gtb = g_gt + (size_t)b * HWn;
    unsigned* ew = g_edgew + (size_t)b * NWRD;
    unsigned* bw = g_blkw  + (size_t)b * NWRD;

    // ---- phase 1: issue ALL global loads (6 rows x float4 + boundaries) ----
    float4 g[KCH + 2];
    float  bl_[KCH + 2], br_[KCH + 2];   // boundary scalars (lanes 0 / 31)
    #pragma unroll
    for (int k = 0; k < KCH + 2; k++) {
        const int y = yB - 1 + k;
        const bool rv = ((unsigned)y < (unsigned)Hn);
        g[k] = rv ? *(const float4*)(gtb + (size_t)y * Wn + x0v)
                  : make_float4(0.f, 0.f, 0.f, 0.f);
        bl_[k] = (rv && lane == 0  && s > 0)       ? __ldg(gtb + (size_t)y * Wn + x0v - 1) : 0.f;
        br_[k] = (rv && lane == 31 && s < SPN - 1) ? __ldg(gtb + (size_t)y * Wn + x0v + 4) : 0.f;
    }

    // ---- phase 2: shuffles for left/right neighbors ----
    float lf[KCH + 2], rt[KCH + 2];
    #pragma unroll
    for (int k = 0; k < KCH + 2; k++) {
        float u = __shfl_up_sync(0xffffffffu, g[k].w, 1);
        float d = __shfl_down_sync(0xffffffffu, g[k].x, 1);
        lf[k] = (lane == 0)  ? bl_[k] : u;
        rt[k] = (lane == 31) ? br_[k] : d;
    }

    // ---- phase 3: Sobel + bit packing per output row ----
    #pragma unroll
    for (int t8 = 0; t8 < KCH; t8++) {
        const int y = yB + t8;           // 0..1079 (NCHK*KCH == 1080)
        const bool r8 = (y & 7) == 0;
        // rows: A = t8, B = t8+1, N = t8+2
        float av[6] = { lf[t8],   g[t8].x,   g[t8].y,   g[t8].z,   g[t8].w,   rt[t8]   };
        float bv6[6]= { lf[t8+1], g[t8+1].x, g[t8+1].y, g[t8+1].z, g[t8+1].w, rt[t8+1] };
        float nv[6] = { lf[t8+2], g[t8+2].x, g[t8+2].y, g[t8+2].z, g[t8+2].w, rt[t8+2] };

        unsigned nibE = 0u, nibB = 0u;
        #pragma unroll
        for (int i = 0; i < 4; i++) {
            float gx = (av[i+2] - av[i]) + 2.f * (bv6[i+2] - bv6[i]) + (nv[i+2] - nv[i]);
            float gy = (nv[i] - av[i]) + 2.f * (nv[i+1] - av[i+1]) + (nv[i+2] - av[i+2]);
            bool e = sqrtf(gx * gx + gy * gy) > 0.15f;
            // col = s*128 + 4*lane + i; col%8==0 iff i==0 && lane even
            float bv = ((i == 0) && ((lane & 1) == 0)) ? fabsf(gx) : 0.f;
            if (r8) bv = fmaxf(bv, fabsf(gy));
            bool bl = bv > 0.05f;
            nibE |= (unsigned)e  << i;
            nibB |= (unsigned)bl << i;
        }
        unsigned ve = nibE << (4 * (lane & 7));
        unsigned vb = nibB << (4 * (lane & 7));
        ve |= __shfl_xor_sync(0xffffffffu, ve, 1);
        vb |= __shfl_xor_sync(0xffffffffu, vb, 1);
        ve |= __shfl_xor_sync(0xffffffffu, ve, 2);
        vb |= __shfl_xor_sync(0xffffffffu, vb, 2);
        ve |= __shfl_xor_sync(0xffffffffu, ve, 4);
        vb |= __shfl_xor_sync(0xffffffffu, vb, 4);
        if ((lane & 7) == 0) {
            const int w = s * 4 + (lane >> 3);
            ew[y * NSPAN + w] = ve;
            bw[y * NSPAN + w] = vb;
        }
    }
}

// ---------------- K3: pure streaming output kernel (no smem, no barriers) --
// block (32,8); thread = col gx, rows yb..yb+3. grid (60, 34, 4).
__global__ __launch_bounds__(256) void k3_out(float* __restrict__ diag) {
    const int lane = threadIdx.x;
    const int ty   = threadIdx.y;
    const int s    = blockIdx.x;
    const int b    = blockIdx.z;
    const int yb   = blockIdx.y * 32 + ty * 4;
    const int gx   = s * 32 + lane;

    const __half2* hqb = g_hrt + (size_t)b * HWn;
    const __half2* dcp = g_dc  + (size_t)b * HWn;
    const unsigned* ew = g_edgew + (size_t)b * NWRD;
    const unsigned* bw = g_blkw  + (size_t)b * NWRD;
    float* o_an = diag + ((size_t)b * 5 + 0) * HWn;
    float* o_cm = diag + ((size_t)b * 5 + 1) * HWn;
    float* o_ss = diag + ((size_t)b * 5 + 2) * HWn;
    float* o_bl = diag + ((size_t)b * 5 + 3) * HWn;
    float* o_ri = diag + ((size_t)b * 5 + 4) * HWn;

    // ---- hrt vertical windows: rows yb-3 .. yb+6 ----
    float2 h[10];
    #pragma unroll
    for (int k = 0; k < 10; k++) {
        int y = yb - 3 + k;
        h[k] = ((unsigned)y < (unsigned)Hn)
             ? __half22float2(__ldg(hqb + (size_t)y * Wn + gx))
             : make_float2(0.f, 0.f);
    }
    float mur[4], mut[4];
    #pragma unroll
    for (int q = 0; q < 4; q++) {
        float sr = 0.f, st = 0.f;
        #pragma unroll
        for (int k = 0; k < 7; k++) { sr += h[q + k].x; st += h[q + k].y; }
        mur[q] = sr; mut[q] = st;
    }

    // ---- dc for the 4 output pixels ----
    __half2 pdc[4];
    #pragma unroll
    for (int r = 0; r < 4; r++) {
        int y = yb + r;
        pdc[r] = (y < Hn) ? __ldg(dcp + (size_t)y * Wn + gx) : __half2(__float2half2_rn(0.f));
    }

    // ---- gather mask words via lane-split load + shuffles ----
    unsigned v = 0u;
    {
        const int r = lane & 7;
        const int row = yb - 2 + r;
        const bool okr = ((unsigned)row < (unsigned)Hn);
        if (lane < 8) {
            if (okr) v = __ldg(ew + row * NSPAN + s);
        } else if (lane < 16) {
            if (okr && s > 0) v = __ldg(ew + row * NSPAN + s - 1);
        } else if (lane < 24) {
            if (okr && s < NSPAN - 1) v = __ldg(ew + row * NSPAN + s + 1);
        } else {
            const int q = lane - 24;
            const int row2 = yb + q;
            if (q < 4 && row2 < Hn) v = __ldg(bw + row2 * NSPAN + s);
        }
    }
    unsigned ec[8], hd[8], bkw[4];
    #pragma unroll
    for (int r = 0; r < 8; r++) {
        unsigned cw = __shfl_sync(0xffffffffu, v, r);
        unsigned pw = __shfl_sync(0xffffffffu, v, 8 + r);
        unsigned nw = __shfl_sync(0xffffffffu, v, 16 + r);
        ec[r] = cw;
        hd[r] = cw | (cw << 1) | (cw << 2) | (cw >> 1) | (cw >> 2)
              | (pw >> 30) | (pw >> 31) | (nw << 30) | (nw << 31);
    }
    #pragma unroll
    for (int q = 0; q < 4; q++) bkw[q] = __shfl_sync(0xffffffffu, v, 24 + q);

    const float invd  = g_invd;
    const float invcd = g_invcd;

    #pragma unroll
    for (int q = 0; q < 4; q++) {
        const int y = yb + q;
        if (y >= Hn) break;

        unsigned dw = hd[q] | hd[q + 1] | hd[q + 2] | hd[q + 3] | hd[q + 4];
        float dil = (float)((dw        >> lane) & 1u);
        float e   = (float)((ec[q + 2] >> lane) & 1u);
        float bk  = (float)((bkw[q]    >> lane) & 1u);

        float mu_r = mur[q] * (1.f / 49.f), mu_t = mut[q] * (1.f / 49.f);
        float ssim = (2.f * mu_r * mu_t + 1e-4f) / (mu_r * mu_r + mu_t * mu_t + 1e-4f);

        float2 dc = __half22float2(pdc[q]);
        float an  = dc.x * invd;
        float cm  = dc.y * invcd;
        float ring = fmaxf(dil - e, 0.f) * an;

        const size_t idx = (size_t)y * Wn + gx;
        o_an[idx] = an;
        o_cm[idx] = cm;
        o_ss[idx] = ssim;
        o_bl[idx] = bk;
        o_ri[idx] = ring;
    }
}

// ---------------- launch ---------------------------------------------------
extern "C" void kernel_launch(void* const* d_in, const int* in_sizes, int n_in,
                              void* d_out, int out_size) {
    const float* ref = (const float*)d_in[0];
    const float* tgt = (const float*)d_in[1];
    float* out = (float*)d_out;

    k0_init<<<1, 32>>>();

    dim3 g1(Hn, Bn);
    k1_point<<<g1, 480>>>(ref, tgt);

    k2_score<<<1, 32>>>(out);

    k2b_edge<<<(SPN * NCHK * Bn + 7) / 8, 256>>>();

    dim3 g3(NSPAN, (Hn + 31) / 32, Bn);
    dim3 b3(32, 8);
    k3_out<<<g3, b3>>>(out + Bn);
}

// round 13
// speedup vs baseline: 1.1049x; 1.1049x over previous
#include <cuda_runtime.h>
#include <cuda_fp16.h>
#include <math.h>

#define Bn 4
#define Hn 1080
#define Wn 1920
#define HWn (Hn * Wn)   // 2073600
#define NSPAN 60        // 1920 / 32 (bit-words per row)
#define NWRD  (Hn * NSPAN)
#define RPB   4         // rows per k1 block

// ---------------- scratch (no runtime allocation allowed) ----------------
__device__ __align__(16) __half2 g_dc [Bn * HWn];   // (sqrt-diff, color-diff) fp16
__device__ __align__(16) __half2 g_hrt[Bn * HWn];   // (hsum7_ref, hsum7_tgt) fp16
__device__ __align__(16) unsigned g_edgew[Bn * NWRD];  // edge bits, 1/px
__device__ __align__(16) unsigned g_blkw [Bn * NWRD];  // blocking bits, 1/px
__device__ int   g_maxd_i;
__device__ int   g_maxcd_i;
__device__ float g_sum[Bn];
__device__ float g_invd, g_invcd;

static __forceinline__ __device__ unsigned h2u(__half2 h) {
    return *reinterpret_cast<unsigned*>(&h);
}

// ---------------- K0: zero reduction scalars ------------------------------
__global__ void k0_init() {
    int t = threadIdx.x;
    if (t == 0) g_maxd_i = 0;
    if (t == 1) g_maxcd_i = 0;
    if (t >= 2 && t < 2 + Bn) g_sum[t - 2] = 0.f;
}

// ---------------- K1: fused pointwise + h-sums + Sobel bit-words ----------
// Block = 480 threads, 4 rows. Each thread owns float4 cols 4t..4t+3.
// SMEM: sgt = tgt gray rows yB-1..yB+4 (6), sgr = ref gray rows yB..yB+3 (4).
__global__ __launch_bounds__(480) void k1_fused(const float* __restrict__ ref,
                                                const float* __restrict__ tgt) {
    const int yB = blockIdx.x * RPB;
    const int b  = blockIdx.y;
    const int t  = threadIdx.x;          // 0..479
    const int lane = t & 31;

    __shared__ __align__(16) float sgt[6][1936];  // col c at index c+4; pads 0
    __shared__ __align__(16) float sgr[4][1936];
    __shared__ float smx[15], smc[15], sms[15];

    // zero the 4-wide pads on both sides
    if (t < 24)      { sgt[t >> 2][t & 3] = 0.f; sgt[t >> 2][1924 + (t & 3)] = 0.f; }
    else if (t < 40) { int q = t - 24; sgr[q >> 2][q & 3] = 0.f; sgr[q >> 2][1924 + (q & 3)] = 0.f; }

    const float* Rb = ref + (size_t)b * 3 * HWn;
    const float* Tb = tgt + (size_t)b * 3 * HWn;
    float lmaxd = 0.f, lmaxcd = 0.f, lsum = 0.f;

    // ---- own rows: pointwise + gray staging ----
    #pragma unroll
    for (int r = 0; r < RPB; r++) {
        const int y = yB + r;
        const int v = (y * Wn) / 4 + t;          // float4 index in plane

        float4 r0 = ((const float4*)(Rb           ))[v];
        float4 r1 = ((const float4*)(Rb +     HWn))[v];
        float4 r2 = ((const float4*)(Rb + 2 * HWn))[v];
        float4 t0 = ((const float4*)(Tb           ))[v];
        float4 t1 = ((const float4*)(Tb +     HWn))[v];
        float4 t2 = ((const float4*)(Tb + 2 * HWn))[v];

        float4 D, C, GR, GT;
#define LANE(c)                                                               \
        {                                                                     \
            float d0 = r0.c - t0.c, d1 = r1.c - t1.c, d2 = r2.c - t2.c;       \
            float df = sqrtf(d0 * d0 + d1 * d1 + d2 * d2);                    \
            float cd = (fabsf(d0) + fabsf(d1) + fabsf(d2)) * (1.f / 3.f);     \
            D.c = df; C.c = cd;                                               \
            GR.c = 0.299f * r0.c + 0.587f * r1.c + 0.114f * r2.c;             \
            GT.c = 0.299f * t0.c + 0.587f * t1.c + 0.114f * t2.c;             \
            lmaxd = fmaxf(lmaxd, df); lmaxcd = fmaxf(lmaxcd, cd);             \
            lsum += df;                                                       \
        }
        LANE(x) LANE(y) LANE(z) LANE(w)
#undef LANE

        uint4 dc;
        dc.x = h2u(__floats2half2_rn(D.x, C.x));
        dc.y = h2u(__floats2half2_rn(D.y, C.y));
        dc.z = h2u(__floats2half2_rn(D.z, C.z));
        dc.w = h2u(__floats2half2_rn(D.w, C.w));
        ((uint4*)(g_dc + (size_t)b * HWn))[v] = dc;

        *(float4*)&sgr[r][4 + 4 * t]     = GR;
        *(float4*)&sgt[r + 1][4 + 4 * t] = GT;
    }

    // ---- halo gray rows (tgt only): yB-1 -> sgt[0], yB+4 -> sgt[5] ----
    #pragma unroll
    for (int hseq = 0; hseq < 2; hseq++) {
        const int y = (hseq == 0) ? (yB - 1) : (yB + RPB);
        const int dst = (hseq == 0) ? 0 : 5;
        float4 GT = make_float4(0.f, 0.f, 0.f, 0.f);
        if ((unsigned)y < (unsigned)Hn) {
            const int v = (y * Wn) / 4 + t;
            float4 t0 = ((const float4*)(Tb           ))[v];
            float4 t1 = ((const float4*)(Tb +     HWn))[v];
            float4 t2 = ((const float4*)(Tb + 2 * HWn))[v];
            GT.x = 0.299f * t0.x + 0.587f * t1.x + 0.114f * t2.x;
            GT.y = 0.299f * t0.y + 0.587f * t1.y + 0.114f * t2.y;
            GT.z = 0.299f * t0.z + 0.587f * t1.z + 0.114f * t2.z;
            GT.w = 0.299f * t0.w + 0.587f * t1.w + 0.114f * t2.w;
        }
        *(float4*)&sgt[dst][4 + 4 * t] = GT;
    }

    // ---- block reduction (overlaps with smem fill settling) ----
    #pragma unroll
    for (int o = 16; o > 0; o >>= 1) {
        lmaxd  = fmaxf(lmaxd,  __shfl_xor_sync(0xffffffffu, lmaxd,  o));
        lmaxcd = fmaxf(lmaxcd, __shfl_xor_sync(0xffffffffu, lmaxcd, o));
        lsum  +=               __shfl_xor_sync(0xffffffffu, lsum,   o);
    }
    const int wid = t >> 5;
    if (lane == 0) { smx[wid] = lmaxd; smc[wid] = lmaxcd; sms[wid] = lsum; }
    __syncthreads();
    if (t == 0) {
        float mx = smx[0], mc = smc[0], s = sms[0];
        #pragma unroll
        for (int i = 1; i < 15; i++) {
            mx = fmaxf(mx, smx[i]); mc = fmaxf(mc, smc[i]); s += sms[i];
        }
        atomicMax(&g_maxd_i,  __float_as_int(mx));
        atomicMax(&g_maxcd_i, __float_as_int(mc));
        atomicAdd(&g_sum[b], s);
    }

    unsigned* ew = g_edgew + (size_t)b * NWRD;
    unsigned* bw = g_blkw  + (size_t)b * NWRD;

    // ---- per row: horizontal 7-sums + Sobel bit-words ----
    #pragma unroll
    for (int r = 0; r < RPB; r++) {
        const int y = yB + r;

        // h-sums: window cols 4t-3..4t+3 (index i holds col i-4)
        const float* ar = &sgr[r][4 * t];
        const float* at = &sgt[r + 1][4 * t];
        float4 A0 = *(const float4*)(ar), A1 = *(const float4*)(ar + 4), A2 = *(const float4*)(ar + 8);
        float4 B0 = *(const float4*)(at), B1 = *(const float4*)(at + 4), B2 = *(const float4*)(at + 8);
        float a[12] = {A0.x,A0.y,A0.z,A0.w, A1.x,A1.y,A1.z,A1.w, A2.x,A2.y,A2.z,A2.w};
        float c[12] = {B0.x,B0.y,B0.z,B0.w, B1.x,B1.y,B1.z,B1.w, B2.x,B2.y,B2.z,B2.w};

        float hr0 = a[1]+a[2]+a[3]+a[4]+a[5]+a[6]+a[7];
        float ht0 = c[1]+c[2]+c[3]+c[4]+c[5]+c[6]+c[7];
        float hr1 = hr0 + a[8] - a[1], ht1 = ht0 + c[8] - c[1];
        float hr2 = hr1 + a[9] - a[2], ht2 = ht1 + c[9] - c[2];
        float hr3 = hr2 + a[10] - a[3], ht3 = ht2 + c[10] - c[3];

        uint4 hq;
        hq.x = h2u(__floats2half2_rn(hr0, ht0));
        hq.y = h2u(__floats2half2_rn(hr1, ht1));
        hq.z = h2u(__floats2half2_rn(hr2, ht2));
        hq.w = h2u(__floats2half2_rn(hr3, ht3));
        ((uint4*)(g_hrt + (size_t)b * HWn))[(y * Wn) / 4 + t] = hq;

        // Sobel rows y-1, y, y+1 = sgt[r], sgt[r+1], sgt[r+2]
        float4 a4 = *(const float4*)&sgt[r][4 + 4 * t];
        float4 b4 = *(const float4*)&sgt[r + 1][4 + 4 * t];
        float4 n4 = *(const float4*)&sgt[r + 2][4 + 4 * t];
        float av[6] = { sgt[r][3 + 4 * t],     a4.x, a4.y, a4.z, a4.w, sgt[r][8 + 4 * t] };
        float bv6[6]= { sgt[r + 1][3 + 4 * t], b4.x, b4.y, b4.z, b4.w, sgt[r + 1][8 + 4 * t] };
        float nv[6] = { sgt[r + 2][3 + 4 * t], n4.x, n4.y, n4.z, n4.w, sgt[r + 2][8 + 4 * t] };

        const bool r8 = (y & 7) == 0;
        unsigned nibE = 0u, nibB = 0u;
        #pragma unroll
        for (int i = 0; i < 4; i++) {
            float gx = (av[i+2] - av[i]) + 2.f * (bv6[i+2] - bv6[i]) + (nv[i+2] - nv[i]);
            float gy = (nv[i] - av[i]) + 2.f * (nv[i+1] - av[i+1]) + (nv[i+2] - av[i+2]);
            bool e = sqrtf(gx * gx + gy * gy) > 0.15f;
            // col = 4t + i; col%8==0 iff i==0 && t even
            float bv = ((i == 0) && ((t & 1) == 0)) ? fabsf(gx) : 0.f;
            if (r8) bv = fmaxf(bv, fabsf(gy));
            bool bl = bv > 0.05f;
            nibE |= (unsigned)e  << i;
            nibB |= (unsigned)bl << i;
        }
        unsigned ve = nibE << (4 * (lane & 7));
        unsigned vb = nibB << (4 * (lane & 7));
        ve |= __shfl_xor_sync(0xffffffffu, ve, 1);
        vb |= __shfl_xor_sync(0xffffffffu, vb, 1);
        ve |= __shfl_xor_sync(0xffffffffu, ve, 2);
        vb |= __shfl_xor_sync(0xffffffffu, vb, 2);
        ve |= __shfl_xor_sync(0xffffffffu, ve, 4);
        vb |= __shfl_xor_sync(0xffffffffu, vb, 4);
        if ((lane & 7) == 0) {
            const int w = t >> 3;       // global word index = (4t)/32
            ew[y * NSPAN + w] = ve;
            bw[y * NSPAN + w] = vb;
        }
    }
}

// ---------------- K2: score + inverse normalizers ------------------------
__global__ void k2_score(float* __restrict__ out) {
    const int t = threadIdx.x;
    const float invd  = 1.f / (__int_as_float(g_maxd_i)  + 1e-12f);
    const float invcd = 1.f / (__int_as_float(g_maxcd_i) + 1e-12f);
    if (t == 0) { g_invd = invd; g_invcd = invcd; }
    if (t < Bn) {
        float m = g_sum[t] * (1.f / (float)HWn) * invd;
        out[t] = fminf(fmaxf(1.f - m, 0.f), 1.f);
    }
}

// ---------------- K3: pure streaming output kernel (no smem, no barriers) --
// block (32,8); thread = col gx, rows yb..yb+3. grid (60, 34, 4).
__global__ __launch_bounds__(256) void k3_out(float* __restrict__ diag) {
    const int lane = threadIdx.x;
    const int ty   = threadIdx.y;
    const int s    = blockIdx.x;
    const int b    = blockIdx.z;
    const int yb   = blockIdx.y * 32 + ty * 4;
    const int gx   = s * 32 + lane;

    const __half2* hqb = g_hrt + (size_t)b * HWn;
    const __half2* dcp = g_dc  + (size_t)b * HWn;
    const unsigned* ew = g_edgew + (size_t)b * NWRD;
    const unsigned* bw = g_blkw  + (size_t)b * NWRD;
    float* o_an = diag + ((size_t)b * 5 + 0) * HWn;
    float* o_cm = diag + ((size_t)b * 5 + 1) * HWn;
    float* o_ss = diag + ((size_t)b * 5 + 2) * HWn;
    float* o_bl = diag + ((size_t)b * 5 + 3) * HWn;
    float* o_ri = diag + ((size_t)b * 5 + 4) * HWn;

    // ---- hrt vertical windows: rows yb-3 .. yb+6 ----
    float2 h[10];
    #pragma unroll
    for (int k = 0; k < 10; k++) {
        int y = yb - 3 + k;
        h[k] = ((unsigned)y < (unsigned)Hn)
             ? __half22float2(__ldg(hqb + (size_t)y * Wn + gx))
             : make_float2(0.f, 0.f);
    }
    float mur[4], mut[4];
    #pragma unroll
    for (int q = 0; q < 4; q++) {
        float sr = 0.f, st = 0.f;
        #pragma unroll
        for (int k = 0; k < 7; k++) { sr += h[q + k].x; st += h[q + k].y; }
        mur[q] = sr; mut[q] = st;
    }

    // ---- dc for the 4 output pixels ----
    __half2 pdc[4];
    #pragma unroll
    for (int r = 0; r < 4; r++) {
        int y = yb + r;
        pdc[r] = (y < Hn) ? __ldg(dcp + (size_t)y * Wn + gx) : __half2(__float2half2_rn(0.f));
    }

    // ---- gather mask words via lane-split load + shuffles ----
    unsigned v = 0u;
    {
        const int r = lane & 7;
        const int row = yb - 2 + r;
        const bool okr = ((unsigned)row < (unsigned)Hn);
        if (lane < 8) {
            if (okr) v = __ldg(ew + row * NSPAN + s);
        } else if (lane < 16) {
            if (okr && s > 0) v = __ldg(ew + row * NSPAN + s - 1);
        } else if (lane < 24) {
            if (okr && s < NSPAN - 1) v = __ldg(ew + row * NSPAN + s + 1);
        } else {
            const int q = lane - 24;
            const int row2 = yb + q;
            if (q < 4 && row2 < Hn) v = __ldg(bw + row2 * NSPAN + s);
        }
    }
    unsigned ec[8], hd[8], bkw[4];
    #pragma unroll
    for (int r = 0; r < 8; r++) {
        unsigned cw = __shfl_sync(0xffffffffu, v, r);
        unsigned pw = __shfl_sync(0xffffffffu, v, 8 + r);
        unsigned nw = __shfl_sync(0xffffffffu, v, 16 + r);
        ec[r] = cw;
        hd[r] = cw | (cw << 1) | (cw << 2) | (cw >> 1) | (cw >> 2)
              | (pw >> 30) | (pw >> 31) | (nw << 30) | (nw << 31);
    }
    #pragma unroll
    for (int q = 0; q < 4; q++) bkw[q] = __shfl_sync(0xffffffffu, v, 24 + q);

    const float invd  = g_invd;
    const float invcd = g_invcd;

    #pragma unroll
    for (int q = 0; q < 4; q++) {
        const int y = yb + q;
        if (y >= Hn) break;

        unsigned dw = hd[q] | hd[q + 1] | hd[q + 2] | hd[q + 3] | hd[q + 4];
        float dil = (float)((dw        >> lane) & 1u);
        float e   = (float)((ec[q + 2] >> lane) & 1u);
        float bk  = (float)((bkw[q]    >> lane) & 1u);

        float mu_r = mur[q] * (1.f / 49.f), mu_t = mut[q] * (1.f / 49.f);
        float ssim = (2.f * mu_r * mu_t + 1e-4f) / (mu_r * mu_r + mu_t * mu_t + 1e-4f);

        float2 dc = __half22float2(pdc[q]);
        float an  = dc.x * invd;
        float cm  = dc.y * invcd;
        float ring = fmaxf(dil - e, 0.f) * an;

        const size_t idx = (size_t)y * Wn + gx;
        o_an[idx] = an;
        o_cm[idx] = cm;
        o_ss[idx] = ssim;
        o_bl[idx] = bk;
        o_ri[idx] = ring;
    }
}

// ---------------- launch ---------------------------------------------------
extern "C" void kernel_launch(void* const* d_in, const int* in_sizes, int n_in,
                              void* d_out, int out_size) {
    const float* ref = (const float*)d_in[0];
    const float* tgt = (const float*)d_in[1];
    float* out = (float*)d_out;

    k0_init<<<1, 32>>>();

    dim3 g1(Hn / RPB, Bn);
    k1_fused<<<g1, 480>>>(ref, tgt);

    k2_score<<<1, 32>>>(out);

    dim3 g3(NSPAN, (Hn + 31) / 32, Bn);
    dim3 b3(32, 8);
    k3_out<<<g3, b3>>>(out + Bn);
}

// round 14
// speedup vs baseline: 1.1256x; 1.0187x over previous
#include <cuda_runtime.h>
#include <cuda_fp16.h>
#include <math.h>

#define Bn 4
#define Hn 1080
#define Wn 1920
#define HWn (Hn * Wn)   // 2073600
#define NSPAN 60        // 1920 / 32 (bit-words per row)
#define NWRD  (Hn * NSPAN)
#define RPB   4         // rows per k1 block

// ---------------- scratch (no runtime allocation allowed) ----------------
__device__ __align__(16) __half2 g_dc [Bn * HWn];   // (sqrt-diff, color-diff) fp16
__device__ __align__(16) __half2 g_hrt[Bn * HWn];   // (hsum7_ref, hsum7_tgt) fp16
__device__ __align__(16) unsigned g_edgew[Bn * NWRD];  // edge bits, 1/px
__device__ __align__(16) unsigned g_blkw [Bn * NWRD];  // blocking bits, 1/px
__device__ int   g_maxd_i;
__device__ int   g_maxcd_i;
__device__ float g_sum[Bn];
__device__ float g_invd, g_invcd;

static __forceinline__ __device__ unsigned h2u(__half2 h) {
    return *reinterpret_cast<unsigned*>(&h);
}

// ---------------- K0: zero reduction scalars ------------------------------
__global__ void k0_init() {
    int t = threadIdx.x;
    if (t == 0) g_maxd_i = 0;
    if (t == 1) g_maxcd_i = 0;
    if (t >= 2 && t < 2 + Bn) g_sum[t - 2] = 0.f;
}

// ---------------- K1: fused pointwise + h-sums + Sobel bit-words ----------
// Block = 480 threads, 4 rows. Each thread owns float4 cols 4t..4t+3.
// SMEM: sgt fp32 (Sobel, threshold-sensitive) + sgr fp16 (ssim-only) = 62KB.
__global__ __launch_bounds__(480) void k1_fused(const float* __restrict__ ref,
                                                const float* __restrict__ tgt) {
    const int yB = blockIdx.x * RPB;
    const int b  = blockIdx.y;
    const int t  = threadIdx.x;          // 0..479
    const int lane = t & 31;

    __shared__ __align__(16) float  sgt [6][1936];  // col c at index c+4; pads 0
    __shared__ __align__(16) __half sgrh[4][1936];  // ref gray fp16
    __shared__ float smx[15], smc[15], sms[15];

    // zero the 4-wide pads on both sides
    if (t < 24)      { sgt[t >> 2][t & 3] = 0.f; sgt[t >> 2][1924 + (t & 3)] = 0.f; }
    else if (t < 40) {
        int q = t - 24;
        sgrh[q >> 2][q & 3] = __float2half(0.f);
        sgrh[q >> 2][1924 + (q & 3)] = __float2half(0.f);
    }

    const float* Rb = ref + (size_t)b * 3 * HWn;
    const float* Tb = tgt + (size_t)b * 3 * HWn;
    float lmaxd = 0.f, lmaxcd = 0.f, lsum = 0.f;

    // ---- own rows: pointwise + gray staging ----
    #pragma unroll
    for (int r = 0; r < RPB; r++) {
        const int y = yB + r;
        const int v = (y * Wn) / 4 + t;          // float4 index in plane

        float4 r0 = ((const float4*)(Rb           ))[v];
        float4 r1 = ((const float4*)(Rb +     HWn))[v];
        float4 r2 = ((const float4*)(Rb + 2 * HWn))[v];
        float4 t0 = ((const float4*)(Tb           ))[v];
        float4 t1 = ((const float4*)(Tb +     HWn))[v];
        float4 t2 = ((const float4*)(Tb + 2 * HWn))[v];

        float4 D, C, GR, GT;
#define LANE(c)                                                               \
        {                                                                     \
            float d0 = r0.c - t0.c, d1 = r1.c - t1.c, d2 = r2.c - t2.c;       \
            float df = sqrtf(d0 * d0 + d1 * d1 + d2 * d2);                    \
            float cd = (fabsf(d0) + fabsf(d1) + fabsf(d2)) * (1.f / 3.f);     \
            D.c = df; C.c = cd;                                               \
            GR.c = 0.299f * r0.c + 0.587f * r1.c + 0.114f * r2.c;             \
            GT.c = 0.299f * t0.c + 0.587f * t1.c + 0.114f * t2.c;             \
            lmaxd = fmaxf(lmaxd, df); lmaxcd = fmaxf(lmaxcd, cd);             \
            lsum += df;                                                       \
        }
        LANE(x) LANE(y) LANE(z) LANE(w)
#undef LANE

        uint4 dc;
        dc.x = h2u(__floats2half2_rn(D.x, C.x));
        dc.y = h2u(__floats2half2_rn(D.y, C.y));
        dc.z = h2u(__floats2half2_rn(D.z, C.z));
        dc.w = h2u(__floats2half2_rn(D.w, C.w));
        ((uint4*)(g_dc + (size_t)b * HWn))[v] = dc;

        // GR -> fp16 pair-packed store (uint2 = 4 halves, 8B aligned)
        uint2 grh;
        grh.x = h2u(__floats2half2_rn(GR.x, GR.y));
        grh.y = h2u(__floats2half2_rn(GR.z, GR.w));
        *(uint2*)&sgrh[r][4 + 4 * t] = grh;
        *(float4*)&sgt[r + 1][4 + 4 * t] = GT;
    }

    // ---- halo gray rows (tgt only): yB-1 -> sgt[0], yB+4 -> sgt[5] ----
    #pragma unroll
    for (int hseq = 0; hseq < 2; hseq++) {
        const int y = (hseq == 0) ? (yB - 1) : (yB + RPB);
        const int dst = (hseq == 0) ? 0 : 5;
        float4 GT = make_float4(0.f, 0.f, 0.f, 0.f);
        if ((unsigned)y < (unsigned)Hn) {
            const int v = (y * Wn) / 4 + t;
            float4 t0 = ((const float4*)(Tb           ))[v];
            float4 t1 = ((const float4*)(Tb +     HWn))[v];
            float4 t2 = ((const float4*)(Tb + 2 * HWn))[v];
            GT.x = 0.299f * t0.x + 0.587f * t1.x + 0.114f * t2.x;
            GT.y = 0.299f * t0.y + 0.587f * t1.y + 0.114f * t2.y;
            GT.z = 0.299f * t0.z + 0.587f * t1.z + 0.114f * t2.z;
            GT.w = 0.299f * t0.w + 0.587f * t1.w + 0.114f * t2.w;
        }
        *(float4*)&sgt[dst][4 + 4 * t] = GT;
    }

    // ---- block reduction ----
    #pragma unroll
    for (int o = 16; o > 0; o >>= 1) {
        lmaxd  = fmaxf(lmaxd,  __shfl_xor_sync(0xffffffffu, lmaxd,  o));
        lmaxcd = fmaxf(lmaxcd, __shfl_xor_sync(0xffffffffu, lmaxcd, o));
        lsum  +=               __shfl_xor_sync(0xffffffffu, lsum,   o);
    }
    const int wid = t >> 5;
    if (lane == 0) { smx[wid] = lmaxd; smc[wid] = lmaxcd; sms[wid] = lsum; }
    __syncthreads();
    if (t == 0) {
        float mx = smx[0], mc = smc[0], s = sms[0];
        #pragma unroll
        for (int i = 1; i < 15; i++) {
            mx = fmaxf(mx, smx[i]); mc = fmaxf(mc, smc[i]); s += sms[i];
        }
        atomicMax(&g_maxd_i,  __float_as_int(mx));
        atomicMax(&g_maxcd_i, __float_as_int(mc));
        atomicAdd(&g_sum[b], s);
    }

    unsigned* ew = g_edgew + (size_t)b * NWRD;
    unsigned* bw = g_blkw  + (size_t)b * NWRD;

    // ---- per row: horizontal 7-sums + Sobel bit-words ----
    #pragma unroll
    for (int r = 0; r < RPB; r++) {
        const int y = yB + r;

        // ref h-sums from fp16 staging: halves at indices 4t-4 .. 4t+7
        float a[12];
        {
            const uint2 p0 = *(const uint2*)&sgrh[r][4 * t];       // idx 4t-4.. (stored at +4 offset base)
            const uint2 p1 = *(const uint2*)&sgrh[r][4 * t + 4];
            const uint2 p2 = *(const uint2*)&sgrh[r][4 * t + 8];
            float2 f0 = __half22float2(*(const __half2*)&p0.x);
            float2 f1 = __half22float2(*(const __half2*)&p0.y);
            float2 f2 = __half22float2(*(const __half2*)&p1.x);
            float2 f3 = __half22float2(*(const __half2*)&p1.y);
            float2 f4 = __half22float2(*(const __half2*)&p2.x);
            float2 f5 = __half22float2(*(const __half2*)&p2.y);
            a[0]=f0.x; a[1]=f0.y; a[2]=f1.x; a[3]=f1.y;
            a[4]=f2.x; a[5]=f2.y; a[6]=f3.x; a[7]=f3.y;
            a[8]=f4.x; a[9]=f4.y; a[10]=f5.x; a[11]=f5.y;
        }
        const float* at = &sgt[r + 1][4 * t];
        float4 B0 = *(const float4*)(at), B1 = *(const float4*)(at + 4), B2 = *(const float4*)(at + 8);
        float c[12] = {B0.x,B0.y,B0.z,B0.w, B1.x,B1.y,B1.z,B1.w, B2.x,B2.y,B2.z,B2.w};

        float hr0 = a[1]+a[2]+a[3]+a[4]+a[5]+a[6]+a[7];
        float ht0 = c[1]+c[2]+c[3]+c[4]+c[5]+c[6]+c[7];
        float hr1 = hr0 + a[8] - a[1], ht1 = ht0 + c[8] - c[1];
        float hr2 = hr1 + a[9] - a[2], ht2 = ht1 + c[9] - c[2];
        float hr3 = hr2 + a[10] - a[3], ht3 = ht2 + c[10] - c[3];

        uint4 hq;
        hq.x = h2u(__floats2half2_rn(hr0, ht0));
        hq.y = h2u(__floats2half2_rn(hr1, ht1));
        hq.z = h2u(__floats2half2_rn(hr2, ht2));
        hq.w = h2u(__floats2half2_rn(hr3, ht3));
        ((uint4*)(g_hrt + (size_t)b * HWn))[(y * Wn) / 4 + t] = hq;

        // Sobel rows y-1, y, y+1 = sgt[r], sgt[r+1], sgt[r+2]
        float4 a4 = *(const float4*)&sgt[r][4 + 4 * t];
        float4 b4 = *(const float4*)&sgt[r + 1][4 + 4 * t];
        float4 n4 = *(const float4*)&sgt[r + 2][4 + 4 * t];
        float av[6] = { sgt[r][3 + 4 * t],     a4.x, a4.y, a4.z, a4.w, sgt[r][8 + 4 * t] };
        float bv6[6]= { sgt[r + 1][3 + 4 * t], b4.x, b4.y, b4.z, b4.w, sgt[r + 1][8 + 4 * t] };
        float nv[6] = { sgt[r + 2][3 + 4 * t], n4.x, n4.y, n4.z, n4.w, sgt[r + 2][8 + 4 * t] };

        const bool r8 = (y & 7) == 0;
        unsigned nibE = 0u, nibB = 0u;
        #pragma unroll
        for (int i = 0; i < 4; i++) {
            float gx = (av[i+2] - av[i]) + 2.f * (bv6[i+2] - bv6[i]) + (nv[i+2] - nv[i]);
            float gy = (nv[i] - av[i]) + 2.f * (nv[i+1] - av[i+1]) + (nv[i+2] - av[i+2]);
            bool e = sqrtf(gx * gx + gy * gy) > 0.15f;
            // col = 4t + i; col%8==0 iff i==0 && t even
            float bv = ((i == 0) && ((t & 1) == 0)) ? fabsf(gx) : 0.f;
            if (r8) bv = fmaxf(bv, fabsf(gy));
            bool bl = bv > 0.05f;
            nibE |= (unsigned)e  << i;
            nibB |= (unsigned)bl << i;
        }
        unsigned ve = nibE << (4 * (lane & 7));
        unsigned vb = nibB << (4 * (lane & 7));
        ve |= __shfl_xor_sync(0xffffffffu, ve, 1);
        vb |= __shfl_xor_sync(0xffffffffu, vb, 1);
        ve |= __shfl_xor_sync(0xffffffffu, ve, 2);
        vb |= __shfl_xor_sync(0xffffffffu, vb, 2);
        ve |= __shfl_xor_sync(0xffffffffu, ve, 4);
        vb |= __shfl_xor_sync(0xffffffffu, vb, 4);
        if ((lane & 7) == 0) {
            const int w = t >> 3;       // global word index = (4t)/32
            ew[y * NSPAN + w] = ve;
            bw[y * NSPAN + w] = vb;
        }
    }
}

// ---------------- K2: score + inverse normalizers ------------------------
__global__ void k2_score(float* __restrict__ out) {
    const int t = threadIdx.x;
    const float invd  = 1.f / (__int_as_float(g_maxd_i)  + 1e-12f);
    const float invcd = 1.f / (__int_as_float(g_maxcd_i) + 1e-12f);
    if (t == 0) { g_invd = invd; g_invcd = invcd; }
    if (t < Bn) {
        float m = g_sum[t] * (1.f / (float)HWn) * invd;
        out[t] = fminf(fmaxf(1.f - m, 0.f), 1.f);
    }
}

// ---------------- K3: pure streaming output kernel (no smem, no barriers) --
// block (32,8); thread = col gx, rows yb..yb+3. grid (60, 34, 4).
__global__ __launch_bounds__(256) void k3_out(float* __restrict__ diag) {
    const int lane = threadIdx.x;
    const int ty   = threadIdx.y;
    const int s    = blockIdx.x;
    const int b    = blockIdx.z;
    const int yb   = blockIdx.y * 32 + ty * 4;
    const int gx   = s * 32 + lane;

    const __half2* hqb = g_hrt + (size_t)b * HWn;
    const __half2* dcp = g_dc  + (size_t)b * HWn;
    const unsigned* ew = g_edgew + (size_t)b * NWRD;
    const unsigned* bw = g_blkw  + (size_t)b * NWRD;
    float* o_an = diag + ((size_t)b * 5 + 0) * HWn;
    float* o_cm = diag + ((size_t)b * 5 + 1) * HWn;
    float* o_ss = diag + ((size_t)b * 5 + 2) * HWn;
    float* o_bl = diag + ((size_t)b * 5 + 3) * HWn;
    float* o_ri = diag + ((size_t)b * 5 + 4) * HWn;

    // ---- hrt vertical windows: rows yb-3 .. yb+6 ----
    float2 h[10];
    #pragma unroll
    for (int k = 0; k < 10; k++) {
        int y = yb - 3 + k;
        h[k] = ((unsigned)y < (unsigned)Hn)
             ? __half22float2(__ldg(hqb + (size_t)y * Wn + gx))
             : make_float2(0.f, 0.f);
    }
    float mur[4], mut[4];
    #pragma unroll
    for (int q = 0; q < 4; q++) {
        float sr = 0.f, st = 0.f;
        #pragma unroll
        for (int k = 0; k < 7; k++) { sr += h[q + k].x; st += h[q + k].y; }
        mur[q] = sr; mut[q] = st;
    }

    // ---- dc for the 4 output pixels ----
    __half2 pdc[4];
    #pragma unroll
    for (int r = 0; r < 4; r++) {
        int y = yb + r;
        pdc[r] = (y < Hn) ? __ldg(dcp + (size_t)y * Wn + gx) : __half2(__float2half2_rn(0.f));
    }

    // ---- gather mask words via lane-split load + shuffles ----
    unsigned v = 0u;
    {
        const int r = lane & 7;
        const int row = yb - 2 + r;
        const bool okr = ((unsigned)row < (unsigned)Hn);
        if (lane < 8) {
            if (okr) v = __ldg(ew + row * NSPAN + s);
        } else if (lane < 16) {
            if (okr && s > 0) v = __ldg(ew + row * NSPAN + s - 1);
        } else if (lane < 24) {
            if (okr && s < NSPAN - 1) v = __ldg(ew + row * NSPAN + s + 1);
        } else {
            const int q = lane - 24;
            const int row2 = yb + q;
            if (q < 4 && row2 < Hn) v = __ldg(bw + row2 * NSPAN + s);
        }
    }
    unsigned ec[8], hd[8], bkw[4];
    #pragma unroll
    for (int r = 0; r < 8; r++) {
        unsigned cw = __shfl_sync(0xffffffffu, v, r);
        unsigned pw = __shfl_sync(0xffffffffu, v, 8 + r);
        unsigned nw = __shfl_sync(0xffffffffu, v, 16 + r);
        ec[r] = cw;
        hd[r] = cw | (cw << 1) | (cw << 2) | (cw >> 1) | (cw >> 2)
              | (pw >> 30) | (pw >> 31) | (nw << 30) | (nw << 31);
    }
    #pragma unroll
    for (int q = 0; q < 4; q++) bkw[q] = __shfl_sync(0xffffffffu, v, 24 + q);

    const float invd  = g_invd;
    const float invcd = g_invcd;

    #pragma unroll
    for (int q = 0; q < 4; q++) {
        const int y = yb + q;
        if (y >= Hn) break;

        unsigned dw = hd[q] | hd[q + 1] | hd[q + 2] | hd[q + 3] | hd[q + 4];
        float dil = (float)((dw        >> lane) & 1u);
        float e   = (float)((ec[q + 2] >> lane) & 1u);
        float bk  = (float)((bkw[q]    >> lane) & 1u);

        float mu_r = mur[q] * (1.f / 49.f), mu_t = mut[q] * (1.f / 49.f);
        float ssim = (2.f * mu_r * mu_t + 1e-4f) / (mu_r * mu_r + mu_t * mu_t + 1e-4f);

        float2 dc = __half22float2(pdc[q]);
        float an  = dc.x * invd;
        float cm  = dc.y * invcd;
        float ring = fmaxf(dil - e, 0.f) * an;

        const size_t idx = (size_t)y * Wn + gx;
        o_an[idx] = an;
        o_cm[idx] = cm;
        o_ss[idx] = ssim;
        o_bl[idx] = bk;
        o_ri[idx] = ring;
    }
}

// ---------------- launch ---------------------------------------------------
extern "C" void kernel_launch(void* const* d_in, const int* in_sizes, int n_in,
                              void* d_out, int out_size) {
    const float* ref = (const float*)d_in[0];
    const float* tgt = (const float*)d_in[1];
    float* out = (float*)d_out;

    k0_init<<<1, 32>>>();

    dim3 g1(Hn / RPB, Bn);
    k1_fused<<<g1, 480>>>(ref, tgt);

    k2_score<<<1, 32>>>(out);

    dim3 g3(NSPAN, (Hn + 31) / 32, Bn);
    dim3 b3(32, 8);
    k3_out<<<g3, b3>>>(out + Bn);
}